// round 16
// baseline (speedup 1.0000x reference)
#include <cuda_runtime.h>
#include <cuda_fp16.h>
#include <cstdint>

// ---------------------------------------------------------------------------
// Problem constants
// ---------------------------------------------------------------------------
#define NMAX 100000
#define EMAX 500000
#define H4   4

// ---------------------------------------------------------------------------
// Static device scratch
// ---------------------------------------------------------------------------
__device__ float g_hp[NMAX * 128];
__device__ float g_ha[NMAX * 128];
__device__ float g_ha2[NMAX * 64];     // layer-2 author hidden (dedicated, no aliasing)
__device__ float g_zp[NMAX * 128];
__device__ float g_za[NMAX * 128];
__device__ float g_asrc_pa[NMAX * H4];
__device__ float g_adst_pa[NMAX * H4];
__device__ float g_asrc_ap[NMAX * H4];
__device__ float g_adst_ap[NMAX * H4];
__device__ int   g_offs_pa[NMAX + 1];
__device__ int   g_offs_ap[NMAX + 1];
__device__ int   g_srcs_pa[EMAX];
__device__ int   g_srcs_ap[EMAX];
__device__ int   g_cnt[NMAX];
__device__ int   g_cnt2[NMAX];
__device__ int   g_partials[256];
__device__ int   g_partials2[256];
// pre-split weights: [n][K] layout, hi/lo fp16.  4 slots: p1,a1,p2,a2
__device__ __half g_wh[4][128 * 128];
__device__ __half g_wl[4][128 * 128];

// ---------------------------------------------------------------------------
// CSR build: histogram -> scan -> scatter
// ---------------------------------------------------------------------------
__global__ void hist_kernel(const int* __restrict__ dst, int E, int* __restrict__ cnt) {
    int e = blockIdx.x * blockDim.x + threadIdx.x;
    if (e < E) atomicAdd(&cnt[dst[e]], 1);
}

__global__ void scan_phase1(const int* __restrict__ in, int n,
                            int* __restrict__ offs, int* __restrict__ partials) {
    __shared__ int sh[1024];
    int t = threadIdx.x;
    int i = blockIdx.x * 1024 + t;
    sh[t] = (i < n) ? in[i] : 0;
    __syncthreads();
    #pragma unroll
    for (int off = 1; off < 1024; off <<= 1) {
        int x = (t >= off) ? sh[t - off] : 0;
        __syncthreads();
        sh[t] += x;
        __syncthreads();
    }
    if (i < n) offs[i + 1] = sh[t];
    if (t == 1023) partials[blockIdx.x] = sh[t];
}

__global__ void scan_phase2(int* __restrict__ partials, int nb) {
    __shared__ int sh[256];
    int t = threadIdx.x;
    sh[t] = (t < nb) ? partials[t] : 0;
    __syncthreads();
    #pragma unroll
    for (int off = 1; off < 256; off <<= 1) {
        int x = (t >= off) ? sh[t - off] : 0;
        __syncthreads();
        sh[t] += x;
        __syncthreads();
    }
    if (t < nb) partials[t] = (t == 0) ? 0 : sh[t - 1];  // exclusive
}

__global__ void scan_phase3(int* __restrict__ offs, const int* __restrict__ partials, int n) {
    int i = blockIdx.x * 1024 + threadIdx.x;
    if (i < n) offs[i + 1] += partials[blockIdx.x];
    if (i == 0) offs[0] = 0;
}

__global__ void scatter_kernel(const int* __restrict__ src, const int* __restrict__ dst,
                               int E, int* __restrict__ cursor, int* __restrict__ out_srcs) {
    int e = blockIdx.x * blockDim.x + threadIdx.x;
    if (e >= E) return;
    int d = dst[e];
    int pos = atomicAdd(&cursor[d], 1);
    out_srcs[pos] = src[e];
}

// ---------------------------------------------------------------------------
// Weight pre-split: W fp32 [K][BN] row-major -> hi/lo fp16 in [n][K] layout.
// ---------------------------------------------------------------------------
__global__ void wsplit_kernel(const float* __restrict__ W,
                              __half* __restrict__ whi, __half* __restrict__ wlo,
                              int K, int BN) {
    int t = blockIdx.x * blockDim.x + threadIdx.x;
    int total = BN * (K / 8);
    if (t >= total) return;
    int n  = t / (K / 8);
    int kq = (t % (K / 8)) * 8;
    uint4 uh, ul;
    uint32_t* ph = (uint32_t*)&uh;
    uint32_t* pl = (uint32_t*)&ul;
    #pragma unroll
    for (int i = 0; i < 4; ++i) {
        float a = W[(size_t)(kq + 2 * i) * BN + n];
        float b = W[(size_t)(kq + 2 * i + 1) * BN + n];
        __half2 h = __floats2half2_rn(a, b);
        float2 f = __half22float2(h);
        __half2 l = __floats2half2_rn(a - f.x, b - f.y);
        ph[i] = *(uint32_t*)&h;
        pl[i] = *(uint32_t*)&l;
    }
    *(uint4*)&whi[(size_t)n * K + kq] = uh;
    *(uint4*)&wlo[(size_t)n * K + kq] = ul;
}

// ---------------------------------------------------------------------------
// MMA / ldmatrix helpers
// ---------------------------------------------------------------------------
__device__ __forceinline__ void mma_f16(float* c, const uint32_t* a, const uint32_t* b) {
    asm volatile(
        "mma.sync.aligned.m16n8k16.row.col.f32.f16.f16.f32 "
        "{%0,%1,%2,%3}, {%4,%5,%6,%7}, {%8,%9}, {%0,%1,%2,%3};\n"
        : "+f"(c[0]), "+f"(c[1]), "+f"(c[2]), "+f"(c[3])
        : "r"(a[0]), "r"(a[1]), "r"(a[2]), "r"(a[3]), "r"(b[0]), "r"(b[1]));
}

__device__ __forceinline__ uint32_t smaddr(const void* p) {
    return (uint32_t)__cvta_generic_to_shared(p);
}

__device__ __forceinline__ void ldsm_x4(uint32_t* r, uint32_t addr) {
    asm volatile("ldmatrix.sync.aligned.m8n8.x4.shared.b16 {%0,%1,%2,%3}, [%4];\n"
                 : "=r"(r[0]), "=r"(r[1]), "=r"(r[2]), "=r"(r[3]) : "r"(addr));
}

__device__ __forceinline__ void ldsm_x2(uint32_t* r, uint32_t addr) {
    asm volatile("ldmatrix.sync.aligned.m8n8.x2.shared.b16 {%0,%1}, [%2];\n"
                 : "=r"(r[0]), "=r"(r[1]) : "r"(addr));
}

__device__ __forceinline__ void split8(const float* va, uint4& uh, uint4& ul) {
    uint32_t* ph = (uint32_t*)&uh;
    uint32_t* pl = (uint32_t*)&ul;
    #pragma unroll
    for (int i = 0; i < 4; ++i) {
        __half2 h = __floats2half2_rn(va[2 * i], va[2 * i + 1]);
        float2 f = __half22float2(h);
        __half2 l = __floats2half2_rn(va[2 * i] - f.x, va[2 * i + 1] - f.y);
        ph[i] = *(uint32_t*)&h;
        pl[i] = *(uint32_t*)&l;
    }
}

// ---------------------------------------------------------------------------
// GEMM: Y[N,BN] = X[N,128] @ W[128,BN] + b, fp16-split 3-pass, ldmatrix loads.
// Double-buffered A staging: ONE __syncthreads per k-tile.
// smem layout: [Ahi0 | Ahi1 | Alo0 | Alo1 | Bhi | Blo]
// ---------------------------------------------------------------------------
template <int BN>
__global__ void __launch_bounds__(256, 2)
gemm_ldm_kernel(const float* __restrict__ X, const __half* __restrict__ Whi,
                const __half* __restrict__ Wlo, const float* __restrict__ bias,
                float* __restrict__ Y, int N) {
    constexpr int K  = 128;
    constexpr int BM = 128;
    constexpr int BK = 16;
    constexpr int AP = 24;
    constexpr int KP = K + 8;
    constexpr int WN = BN / 2;
    constexpr int FRAG_M = 2;
    constexpr int FRAG_N = WN / 8;
    constexpr int ABUF = BM * AP;        // halves per A buffer
    constexpr int NT = K / BK;           // 8 k-tiles

    extern __shared__ __half sm[];
    __half* Bhi = sm + 4 * ABUF;
    __half* Blo = Bhi + BN * KP;

    int tid  = threadIdx.x;
    int wid  = tid >> 5;
    int lane = tid & 31;
    int warp_m = wid & 3;
    int warp_n = wid >> 2;
    int row0 = blockIdx.x * BM;

    // ---- load whole pre-split W into smem (coalesced uint4) ----
    for (int idx = tid * 8; idx < BN * K; idx += 256 * 8) {
        int n = idx >> 7;
        int k = idx & 127;
        *(uint4*)&Bhi[n * KP + k] = *(const uint4*)&Whi[idx];
        *(uint4*)&Blo[n * KP + k] = *(const uint4*)&Wlo[idx];
    }

    float c[FRAG_M][FRAG_N][4];
    #pragma unroll
    for (int i = 0; i < FRAG_M; ++i)
        #pragma unroll
        for (int j = 0; j < FRAG_N; ++j)
            #pragma unroll
            for (int k = 0; k < 4; ++k) c[i][j][k] = 0.f;

    // A staging map
    int xr  = tid >> 1;
    int xkb = (tid & 1) * 8;
    bool xvalid = (row0 + xr) < N;
    const float* xb = X + (size_t)(row0 + xr) * K + xkb;

    // ldmatrix A addresses for both buffers
    uint32_t a_hi_ad[2][FRAG_M], a_lo_ad[2][FRAG_M];
    #pragma unroll
    for (int b = 0; b < 2; ++b)
        #pragma unroll
        for (int fm = 0; fm < FRAG_M; ++fm) {
            int r = warp_m * 32 + fm * 16 + (lane & 15);
            int kofs = (lane >> 4) * 8;
            a_hi_ad[b][fm] = smaddr(&sm[b * ABUF + r * AP + kofs]);
            a_lo_ad[b][fm] = smaddr(&sm[2 * ABUF + b * ABUF + r * AP + kofs]);
        }
    int bn_row = warp_n * WN + (lane & 7);
    int bk_off = ((lane >> 3) & 1) * 8;

    // ---- stage tile 0 into buf 0; prefetch tile 1 ----
    float4 v0 = make_float4(0.f, 0.f, 0.f, 0.f), v1 = v0;
    if (xvalid) { v0 = *(const float4*)(xb); v1 = *(const float4*)(xb + 4); }
    {
        float va[8] = {v0.x, v0.y, v0.z, v0.w, v1.x, v1.y, v1.z, v1.w};
        uint4 uh, ul;
        split8(va, uh, ul);
        *(uint4*)&sm[0 * ABUF + xr * AP + xkb] = uh;
        *(uint4*)&sm[2 * ABUF + xr * AP + xkb] = ul;
    }
    if (xvalid) { v0 = *(const float4*)(xb + BK); v1 = *(const float4*)(xb + BK + 4); }
    __syncthreads();

    for (int t = 0; t < NT; ++t) {
        int kt = t * BK;
        int cur = t & 1;

        // ---- A/B fragments via ldmatrix (current buffer) ----
        uint32_t ah[FRAG_M][4], al[FRAG_M][4];
        #pragma unroll
        for (int fm = 0; fm < FRAG_M; ++fm) {
            ldsm_x4(ah[fm], a_hi_ad[cur][fm]);
            ldsm_x4(al[fm], a_lo_ad[cur][fm]);
        }
        uint32_t bh[FRAG_N][2], bl[FRAG_N][2];
        #pragma unroll
        for (int fn = 0; fn < FRAG_N; ++fn) {
            int nr = (bn_row + fn * 8) * KP + kt + bk_off;
            ldsm_x2(bh[fn], smaddr(&Bhi[nr]));
            ldsm_x2(bl[fn], smaddr(&Blo[nr]));
        }

        // ---- stage next tile into alternate buffer; prefetch tile t+2 ----
        if (t + 1 < NT) {
            int nxt = cur ^ 1;
            float va[8] = {v0.x, v0.y, v0.z, v0.w, v1.x, v1.y, v1.z, v1.w};
            uint4 uh, ul;
            split8(va, uh, ul);
            *(uint4*)&sm[nxt * ABUF + xr * AP + xkb] = uh;
            *(uint4*)&sm[2 * ABUF + nxt * ABUF + xr * AP + xkb] = ul;
            if (t + 2 < NT && xvalid) {
                v0 = *(const float4*)(xb + (t + 2) * BK);
                v1 = *(const float4*)(xb + (t + 2) * BK + 4);
            }
        }

        #pragma unroll
        for (int fm = 0; fm < FRAG_M; ++fm)
            #pragma unroll
            for (int fn = 0; fn < FRAG_N; ++fn) {
                mma_f16(c[fm][fn], ah[fm], bh[fn]);
                mma_f16(c[fm][fn], ah[fm], bl[fn]);
                mma_f16(c[fm][fn], al[fm], bh[fn]);
            }
        __syncthreads();
    }

    // ---- epilogue: add bias, store ----
    int er  = row0 + warp_m * 32 + (lane >> 2);
    int ec0 = warp_n * WN + (lane & 3) * 2;
    #pragma unroll
    for (int fn = 0; fn < FRAG_N; ++fn) {
        int col = ec0 + fn * 8;
        float b0 = bias[col], b1 = bias[col + 1];
        #pragma unroll
        for (int fm = 0; fm < FRAG_M; ++fm) {
            int r = er + fm * 16;
            if (r < N) {
                float2 o = make_float2(c[fm][fn][0] + b0, c[fm][fn][1] + b1);
                *(float2*)&Y[(size_t)r * BN + col] = o;
            }
            if (r + 8 < N) {
                float2 o = make_float2(c[fm][fn][2] + b0, c[fm][fn][3] + b1);
                *(float2*)&Y[(size_t)(r + 8) * BN + col] = o;
            }
        }
    }
}

// ---------------------------------------------------------------------------
// Fused per-node attention logits: one read of H, both src and dst dots.
// ---------------------------------------------------------------------------
template <int F>
__global__ void alpha2_kernel(const float* __restrict__ Hf,
                              const float* __restrict__ avs, const float* __restrict__ avd,
                              float* __restrict__ outs, float* __restrict__ outd, int N) {
    int i = blockIdx.x * blockDim.x + threadIdx.x;
    if (i >= N * H4) return;
    int n = i >> 2, h = i & 3;
    constexpr int D = F / 4;
    const float4* row = (const float4*)(Hf + (size_t)n * F + h * D);
    const float4* as = (const float4*)(avs + h * D);
    const float4* ad = (const float4*)(avd + h * D);
    float ss = 0.f, sd = 0.f;
    #pragma unroll
    for (int d = 0; d < D / 4; ++d) {
        float4 hv = row[d], a = as[d], b = ad[d];
        ss += hv.x * a.x + hv.y * a.y + hv.z * a.z + hv.w * a.w;
        sd += hv.x * b.x + hv.y * b.y + hv.z * b.z + hv.w * b.w;
    }
    outs[i] = ss;
    outd[i] = sd;
}

// ---------------------------------------------------------------------------
// Edge-softmax aggregation, warp per dst node, BATCH-4 online softmax:
// four edges per iteration with a joint running max.  Same math as the
// serial online softmax; rescale chain is ceil(deg/4), four independent
// L2 row-gathers in flight per iteration.
// ---------------------------------------------------------------------------
template <int F>
__global__ void __launch_bounds__(256)
aggregate_kernel(const float* __restrict__ Hsrc, const float* __restrict__ asrc,
                 const float* __restrict__ adst, const int* __restrict__ offs,
                 const int* __restrict__ srcs, float* __restrict__ Out, int Ndst) {
    constexpr int VEC = F / 32;
    int wid = (blockIdx.x * blockDim.x + threadIdx.x) >> 5;
    int lane = threadIdx.x & 31;
    if (wid >= Ndst) return;
    int beg = offs[wid], end = offs[wid + 1];
    int head = lane >> 3;
    float ad = __ldg(&adst[wid * H4 + head]);
    float m = -3.4e38f, l = 0.f;
    float acc[VEC];
    #pragma unroll
    for (int v = 0; v < VEC; ++v) acc[v] = 0.f;

    int j = beg;
    for (; j + 4 <= end; j += 4) {
        int s0 = __ldg(&srcs[j]);
        int s1 = __ldg(&srcs[j + 1]);
        int s2 = __ldg(&srcs[j + 2]);
        int s3 = __ldg(&srcs[j + 3]);
        float a0 = __ldg(&asrc[s0 * H4 + head]) + ad;
        float a1 = __ldg(&asrc[s1 * H4 + head]) + ad;
        float a2 = __ldg(&asrc[s2 * H4 + head]) + ad;
        float a3 = __ldg(&asrc[s3 * H4 + head]) + ad;
        a0 = (a0 >= 0.f) ? a0 : 0.2f * a0;
        a1 = (a1 >= 0.f) ? a1 : 0.2f * a1;
        a2 = (a2 >= 0.f) ? a2 : 0.2f * a2;
        a3 = (a3 >= 0.f) ? a3 : 0.2f * a3;
        float mn = fmaxf(fmaxf(m, fmaxf(a0, a1)), fmaxf(a2, a3));
        float sc = __expf(m - mn);
        float e0 = __expf(a0 - mn);
        float e1 = __expf(a1 - mn);
        float e2 = __expf(a2 - mn);
        float e3 = __expf(a3 - mn);
        l = l * sc + (e0 + e1) + (e2 + e3);
        const float* p0 = Hsrc + (size_t)s0 * F + lane * VEC;
        const float* p1 = Hsrc + (size_t)s1 * F + lane * VEC;
        const float* p2 = Hsrc + (size_t)s2 * F + lane * VEC;
        const float* p3 = Hsrc + (size_t)s3 * F + lane * VEC;
        if (VEC == 4) {
            float4 h0 = __ldg((const float4*)p0);
            float4 h1 = __ldg((const float4*)p1);
            float4 h2 = __ldg((const float4*)p2);
            float4 h3 = __ldg((const float4*)p3);
            acc[0] = acc[0] * sc + (e0 * h0.x + e1 * h1.x) + (e2 * h2.x + e3 * h3.x);
            acc[1] = acc[1] * sc + (e0 * h0.y + e1 * h1.y) + (e2 * h2.y + e3 * h3.y);
            acc[2] = acc[2] * sc + (e0 * h0.z + e1 * h1.z) + (e2 * h2.z + e3 * h3.z);
            acc[3] = acc[3] * sc + (e0 * h0.w + e1 * h1.w) + (e2 * h2.w + e3 * h3.w);
        } else {
            float2 h0 = __ldg((const float2*)p0);
            float2 h1 = __ldg((const float2*)p1);
            float2 h2 = __ldg((const float2*)p2);
            float2 h3 = __ldg((const float2*)p3);
            acc[0] = acc[0] * sc + (e0 * h0.x + e1 * h1.x) + (e2 * h2.x + e3 * h3.x);
            acc[1] = acc[1] * sc + (e0 * h0.y + e1 * h1.y) + (e2 * h2.y + e3 * h3.y);
        }
        m = mn;
    }
    for (; j < end; ++j) {
        int s = __ldg(&srcs[j]);
        float a = __ldg(&asrc[s * H4 + head]) + ad;
        a = (a >= 0.f) ? a : 0.2f * a;
        float mn = fmaxf(m, a);
        float sc = __expf(m - mn);
        float e  = __expf(a - mn);
        l = l * sc + e;
        const float* hp = Hsrc + (size_t)s * F + lane * VEC;
        if (VEC == 4) {
            float4 hv = __ldg((const float4*)hp);
            acc[0] = acc[0] * sc + e * hv.x;
            acc[1] = acc[1] * sc + e * hv.y;
            acc[2] = acc[2] * sc + e * hv.z;
            acc[3] = acc[3] * sc + e * hv.w;
        } else {
            float2 hv = __ldg((const float2*)hp);
            acc[0] = acc[0] * sc + e * hv.x;
            acc[1] = acc[1] * sc + e * hv.y;
        }
        m = mn;
    }
    float inv = 1.f / (l + 1e-16f);
    float* op = Out + (size_t)wid * F + lane * VEC;
    #pragma unroll
    for (int v = 0; v < VEC; ++v) op[v] = fmaxf(acc[v] * inv, 0.f);
}

// ---------------------------------------------------------------------------
// Final link prediction
// ---------------------------------------------------------------------------
__global__ void edge_dot_kernel(const float* __restrict__ zp, const float* __restrict__ za,
                                const int* __restrict__ eli, float* __restrict__ out, int L) {
    int t = blockIdx.x * blockDim.x + threadIdx.x;
    int edge = t >> 4;
    int sub = t & 15;
    if (edge >= L) return;
    int p = eli[edge];
    int a = eli[L + edge];
    float4 u = *(const float4*)(zp + (size_t)p * 64 + sub * 4);
    float4 v = *(const float4*)(za + (size_t)a * 64 + sub * 4);
    float s = u.x * v.x + u.y * v.y + u.z * v.z + u.w * v.w;
    s += __shfl_xor_sync(0xffffffffu, s, 8);
    s += __shfl_xor_sync(0xffffffffu, s, 4);
    s += __shfl_xor_sync(0xffffffffu, s, 2);
    s += __shfl_xor_sync(0xffffffffu, s, 1);
    if (sub == 0) out[edge] = s;
}

// ---------------------------------------------------------------------------
// Host orchestration  (R13/R14 schedule, measured best)
// ---------------------------------------------------------------------------
extern "C" void kernel_launch(void* const* d_in, const int* in_sizes, int n_in,
                              void* d_out, int out_size) {
    const float* x_paper  = (const float*)d_in[0];
    const float* x_author = (const float*)d_in[1];
    const int*   ei_pa    = (const int*)d_in[2];
    const int*   ei_ap    = (const int*)d_in[3];
    const int*   eli      = (const int*)d_in[4];
    const float* p1W = (const float*)d_in[5];
    const float* p1b = (const float*)d_in[6];
    const float* a1W = (const float*)d_in[7];
    const float* a1b = (const float*)d_in[8];
    const float* s1pa = (const float*)d_in[9];
    const float* d1pa = (const float*)d_in[10];
    const float* s1ap = (const float*)d_in[11];
    const float* d1ap = (const float*)d_in[12];
    // d_in[13..15]: k1W,k1b,q1 dead (_group over one metapath == identity)
    const float* p2W = (const float*)d_in[16];
    const float* p2b = (const float*)d_in[17];
    const float* a2W = (const float*)d_in[18];
    const float* a2b = (const float*)d_in[19];
    const float* s2pa = (const float*)d_in[20];
    const float* d2pa = (const float*)d_in[21];
    const float* s2ap = (const float*)d_in[22];
    const float* d2ap = (const float*)d_in[23];
    // d_in[24..26]: k2W,k2b,q2 dead

    int NP = in_sizes[0] / 128;
    int NA = in_sizes[1] / 128;
    int E  = in_sizes[2] / 2;
    int L  = in_sizes[4] / 2;

    float *hp, *ha, *ha2, *zp, *za, *asrc_pa, *adst_pa, *asrc_ap, *adst_ap;
    int *offs_pa, *offs_ap, *srcs_pa, *srcs_ap, *cnt, *cnt2, *partials, *partials2;
    __half *wh, *wl;
    cudaGetSymbolAddress((void**)&hp, g_hp);
    cudaGetSymbolAddress((void**)&ha, g_ha);
    cudaGetSymbolAddress((void**)&ha2, g_ha2);
    cudaGetSymbolAddress((void**)&zp, g_zp);
    cudaGetSymbolAddress((void**)&za, g_za);
    cudaGetSymbolAddress((void**)&asrc_pa, g_asrc_pa);
    cudaGetSymbolAddress((void**)&adst_pa, g_adst_pa);
    cudaGetSymbolAddress((void**)&asrc_ap, g_asrc_ap);
    cudaGetSymbolAddress((void**)&adst_ap, g_adst_ap);
    cudaGetSymbolAddress((void**)&offs_pa, g_offs_pa);
    cudaGetSymbolAddress((void**)&offs_ap, g_offs_ap);
    cudaGetSymbolAddress((void**)&srcs_pa, g_srcs_pa);
    cudaGetSymbolAddress((void**)&srcs_ap, g_srcs_ap);
    cudaGetSymbolAddress((void**)&cnt, g_cnt);
    cudaGetSymbolAddress((void**)&cnt2, g_cnt2);
    cudaGetSymbolAddress((void**)&partials, g_partials);
    cudaGetSymbolAddress((void**)&partials2, g_partials2);
    cudaGetSymbolAddress((void**)&wh, g_wh);
    cudaGetSymbolAddress((void**)&wl, g_wl);
    __half* wh1p = wh;               __half* wl1p = wl;
    __half* wh1a = wh + 16384;       __half* wl1a = wl + 16384;
    __half* wh2p = wh + 2 * 16384;   __half* wl2p = wl + 2 * 16384;
    __half* wh2a = wh + 3 * 16384;   __half* wl2a = wl + 3 * 16384;

    // smem: 4 A buffers (double-buffered hi/lo) + B hi/lo
    constexpr int SM128 = (4 * 128 * 24 + 2 * 128 * 136) * 2;   // 94208
    constexpr int SM64  = (4 * 128 * 24 + 2 * 64 * 136) * 2;    // 59392
    cudaFuncSetAttribute(gemm_ldm_kernel<128>, cudaFuncAttributeMaxDynamicSharedMemorySize, SM128);
    cudaFuncSetAttribute(gemm_ldm_kernel<64>,  cudaFuncAttributeMaxDynamicSharedMemorySize, SM64);

    static cudaStream_t s1 = nullptr;
    static cudaEvent_t evA = nullptr, evB = nullptr, evC = nullptr, evD = nullptr;
    if (!s1) {
        cudaStreamCreateWithFlags(&s1, cudaStreamNonBlocking);
        cudaEventCreateWithFlags(&evA, cudaEventDisableTiming);
        cudaEventCreateWithFlags(&evB, cudaEventDisableTiming);
        cudaEventCreateWithFlags(&evC, cudaEventDisableTiming);
        cudaEventCreateWithFlags(&evD, cudaEventDisableTiming);
    }

    int gb_p = (NP + 127) / 128;
    int gb_a = (NA + 127) / 128;
    int at_p = (NP * H4 + 255) / 256;
    int at_a = (NA * H4 + 255) / 256;
    int ag_a = (NA * 32 + 255) / 256;
    int ag_p = (NP * 32 + 255) / 256;
    int nb   = (NMAX + 1023) / 1024;
    int ws128 = (128 * 16 + 255) / 256;
    int ws64  = (64 * 16 + 255) / 256;
    int eg   = (E + 255) / 256;

    // ---- main stream: kernels 1-3, then the captured GEMM (#4) ----
    wsplit_kernel<<<ws128, 256>>>(p1W, wh1p, wl1p, 128, 128);                 // k1
    hist_kernel<<<eg, 256>>>(ei_pa + E, E, cnt);                              // k2 (cnt zero on entry)
    scan_phase1<<<nb, 1024>>>(cnt, NA, offs_pa, partials);                    // k3
    gemm_ldm_kernel<128><<<gb_p, 256, SM128>>>(x_paper, wh1p, wl1p, p1b, hp, NP);  // k4 <- ncu
    cudaEventRecord(evA, 0);

    // ---- side stream: CSR-ap + layer-2 weight splits (hidden by gemms) ----
    cudaStreamWaitEvent(s1, evA, 0);
    cudaMemsetAsync(cnt2, 0, (size_t)NP * sizeof(int), s1);
    hist_kernel<<<eg, 256, 0, s1>>>(ei_ap + E, E, cnt2);
    scan_phase1<<<nb, 1024, 0, s1>>>(cnt2, NP, offs_ap, partials2);
    scan_phase2<<<1, 256, 0, s1>>>(partials2, nb);
    scan_phase3<<<nb, 1024, 0, s1>>>(offs_ap, partials2, NP);
    cudaMemcpyAsync(cnt2, offs_ap, (size_t)NP * sizeof(int), cudaMemcpyDeviceToDevice, s1);
    scatter_kernel<<<eg, 256, 0, s1>>>(ei_ap, ei_ap + E, E, cnt2, srcs_ap);
    wsplit_kernel<<<ws64, 256, 0, s1>>>(p2W, wh2p, wl2p, 128, 64);
    wsplit_kernel<<<ws64, 256, 0, s1>>>(a2W, wh2a, wl2a, 128, 64);
    cudaEventRecord(evB, s1);

    // ---- main: finish CSR-pa, 2nd gemm, attention ----
    scan_phase2<<<1, 256>>>(partials, nb);
    scan_phase3<<<nb, 1024>>>(offs_pa, partials, NA);
    cudaMemcpyAsync(cnt, offs_pa, (size_t)NA * sizeof(int), cudaMemcpyDeviceToDevice);
    scatter_kernel<<<eg, 256>>>(ei_pa, ei_pa + E, E, cnt, srcs_pa);
    cudaMemsetAsync(cnt, 0, (size_t)NA * sizeof(int));   // re-zero for next call
    wsplit_kernel<<<ws128, 256>>>(a1W, wh1a, wl1a, 128, 128);
    gemm_ldm_kernel<128><<<gb_a, 256, SM128>>>(x_author, wh1a, wl1a, a1b, ha, NA);

    alpha2_kernel<128><<<at_p, 256>>>(hp, s1pa, d1ap, asrc_pa, adst_ap, NP);
    alpha2_kernel<128><<<at_a, 256>>>(ha, s1ap, d1pa, asrc_ap, adst_pa, NA);
    aggregate_kernel<128><<<ag_a, 256>>>(hp, asrc_pa, adst_pa, offs_pa, srcs_pa, za, NA);
    cudaEventRecord(evC, 0);          // za ready

    // side: gemm2a (za -> ha2, dedicated buffer) overlaps agg_ap + gemm2p
    cudaStreamWaitEvent(s1, evC, 0);
    gemm_ldm_kernel<64><<<gb_a, 256, SM64, s1>>>(za, wh2a, wl2a, a2b, ha2, NA);
    cudaEventRecord(evD, s1);

    cudaStreamWaitEvent(0, evB, 0);   // CSR-ap ready
    aggregate_kernel<128><<<ag_p, 256>>>(ha, asrc_ap, adst_ap, offs_ap, srcs_ap, zp, NP);

    // ---- Layer 2 (K=128 -> F=64) ----
    gemm_ldm_kernel<64><<<gb_p, 256, SM64>>>(zp, wh2p, wl2p, p2b, hp, NP);
    alpha2_kernel<64><<<at_p, 256>>>(hp, s2pa, d2ap, asrc_pa, adst_ap, NP);
    cudaStreamWaitEvent(0, evD, 0);   // ha2 ready (also guards za overwrite below)
    alpha2_kernel<64><<<at_a, 256>>>(ha2, s2ap, d2pa, asrc_ap, adst_pa, NA);
    aggregate_kernel<64><<<ag_a, 256>>>(hp, asrc_pa, adst_pa, offs_pa, srcs_pa, za, NA);
    aggregate_kernel<64><<<ag_p, 256>>>(ha2, asrc_ap, adst_ap, offs_ap, srcs_ap, zp, NP);

    // ---- Link prediction ----
    edge_dot_kernel<<<(L * 16 + 255) / 256, 256>>>(zp, za, eli, (float*)d_out, L);
}

// round 17
// speedup vs baseline: 1.0851x; 1.0851x over previous
#include <cuda_runtime.h>
#include <cuda_fp16.h>
#include <cstdint>

// ---------------------------------------------------------------------------
// Problem constants
// ---------------------------------------------------------------------------
#define NMAX 100000
#define EMAX 500000
#define H4   4

// ---------------------------------------------------------------------------
// Static device scratch
// ---------------------------------------------------------------------------
__device__ float g_hp[NMAX * 128];
__device__ float g_ha[NMAX * 128];
__device__ float g_ha2[NMAX * 64];     // layer-2 author hidden (dedicated, no aliasing)
__device__ float g_zp[NMAX * 128];
__device__ float g_za[NMAX * 128];
__device__ float g_asrc_pa[NMAX * H4];
__device__ float g_adst_pa[NMAX * H4];
__device__ float g_asrc_ap[NMAX * H4];
__device__ float g_adst_ap[NMAX * H4];
__device__ int   g_offs_pa[NMAX + 1];
__device__ int   g_offs_ap[NMAX + 1];
__device__ int   g_srcs_pa[EMAX];
__device__ int   g_srcs_ap[EMAX];
__device__ int   g_cnt[NMAX];
__device__ int   g_cnt2[NMAX];
__device__ int   g_partials[256];
__device__ int   g_partials2[256];
// pre-split weights: [n][K] layout, hi/lo fp16.  4 slots: p1,a1,p2,a2
__device__ __half g_wh[4][128 * 128];
__device__ __half g_wl[4][128 * 128];

// ---------------------------------------------------------------------------
// CSR build: histogram -> scan -> scatter
// ---------------------------------------------------------------------------
__global__ void hist_kernel(const int* __restrict__ dst, int E, int* __restrict__ cnt) {
    int e = blockIdx.x * blockDim.x + threadIdx.x;
    if (e < E) atomicAdd(&cnt[dst[e]], 1);
}

__global__ void scan_phase1(const int* __restrict__ in, int n,
                            int* __restrict__ offs, int* __restrict__ partials) {
    __shared__ int sh[1024];
    int t = threadIdx.x;
    int i = blockIdx.x * 1024 + t;
    sh[t] = (i < n) ? in[i] : 0;
    __syncthreads();
    #pragma unroll
    for (int off = 1; off < 1024; off <<= 1) {
        int x = (t >= off) ? sh[t - off] : 0;
        __syncthreads();
        sh[t] += x;
        __syncthreads();
    }
    if (i < n) offs[i + 1] = sh[t];
    if (t == 1023) partials[blockIdx.x] = sh[t];
}

__global__ void scan_phase2(int* __restrict__ partials, int nb) {
    __shared__ int sh[256];
    int t = threadIdx.x;
    sh[t] = (t < nb) ? partials[t] : 0;
    __syncthreads();
    #pragma unroll
    for (int off = 1; off < 256; off <<= 1) {
        int x = (t >= off) ? sh[t - off] : 0;
        __syncthreads();
        sh[t] += x;
        __syncthreads();
    }
    if (t < nb) partials[t] = (t == 0) ? 0 : sh[t - 1];  // exclusive
}

__global__ void scan_phase3(int* __restrict__ offs, const int* __restrict__ partials, int n) {
    int i = blockIdx.x * 1024 + threadIdx.x;
    if (i < n) offs[i + 1] += partials[blockIdx.x];
    if (i == 0) offs[0] = 0;
}

__global__ void scatter_kernel(const int* __restrict__ src, const int* __restrict__ dst,
                               int E, int* __restrict__ cursor, int* __restrict__ out_srcs) {
    int e = blockIdx.x * blockDim.x + threadIdx.x;
    if (e >= E) return;
    int d = dst[e];
    int pos = atomicAdd(&cursor[d], 1);
    out_srcs[pos] = src[e];
}

// ---------------------------------------------------------------------------
// Weight pre-split: W fp32 [K][BN] row-major -> hi/lo fp16 in [n][K] layout.
// ---------------------------------------------------------------------------
__global__ void wsplit_kernel(const float* __restrict__ W,
                              __half* __restrict__ whi, __half* __restrict__ wlo,
                              int K, int BN) {
    int t = blockIdx.x * blockDim.x + threadIdx.x;
    int total = BN * (K / 8);
    if (t >= total) return;
    int n  = t / (K / 8);
    int kq = (t % (K / 8)) * 8;
    uint4 uh, ul;
    uint32_t* ph = (uint32_t*)&uh;
    uint32_t* pl = (uint32_t*)&ul;
    #pragma unroll
    for (int i = 0; i < 4; ++i) {
        float a = W[(size_t)(kq + 2 * i) * BN + n];
        float b = W[(size_t)(kq + 2 * i + 1) * BN + n];
        __half2 h = __floats2half2_rn(a, b);
        float2 f = __half22float2(h);
        __half2 l = __floats2half2_rn(a - f.x, b - f.y);
        ph[i] = *(uint32_t*)&h;
        pl[i] = *(uint32_t*)&l;
    }
    *(uint4*)&whi[(size_t)n * K + kq] = uh;
    *(uint4*)&wlo[(size_t)n * K + kq] = ul;
}

// ---------------------------------------------------------------------------
// MMA / ldmatrix helpers
// ---------------------------------------------------------------------------
__device__ __forceinline__ void mma_f16(float* c, const uint32_t* a, const uint32_t* b) {
    asm volatile(
        "mma.sync.aligned.m16n8k16.row.col.f32.f16.f16.f32 "
        "{%0,%1,%2,%3}, {%4,%5,%6,%7}, {%8,%9}, {%0,%1,%2,%3};\n"
        : "+f"(c[0]), "+f"(c[1]), "+f"(c[2]), "+f"(c[3])
        : "r"(a[0]), "r"(a[1]), "r"(a[2]), "r"(a[3]), "r"(b[0]), "r"(b[1]));
}

__device__ __forceinline__ uint32_t smaddr(const void* p) {
    return (uint32_t)__cvta_generic_to_shared(p);
}

__device__ __forceinline__ void ldsm_x4(uint32_t* r, uint32_t addr) {
    asm volatile("ldmatrix.sync.aligned.m8n8.x4.shared.b16 {%0,%1,%2,%3}, [%4];\n"
                 : "=r"(r[0]), "=r"(r[1]), "=r"(r[2]), "=r"(r[3]) : "r"(addr));
}

__device__ __forceinline__ void ldsm_x2(uint32_t* r, uint32_t addr) {
    asm volatile("ldmatrix.sync.aligned.m8n8.x2.shared.b16 {%0,%1}, [%2];\n"
                 : "=r"(r[0]), "=r"(r[1]) : "r"(addr));
}

__device__ __forceinline__ void split8(const float* va, uint4& uh, uint4& ul) {
    uint32_t* ph = (uint32_t*)&uh;
    uint32_t* pl = (uint32_t*)&ul;
    #pragma unroll
    for (int i = 0; i < 4; ++i) {
        __half2 h = __floats2half2_rn(va[2 * i], va[2 * i + 1]);
        float2 f = __half22float2(h);
        __half2 l = __floats2half2_rn(va[2 * i] - f.x, va[2 * i + 1] - f.y);
        ph[i] = *(uint32_t*)&h;
        pl[i] = *(uint32_t*)&l;
    }
}

// ---------------------------------------------------------------------------
// GEMM: Y[N,BN] = X[N,128] @ W[128,BN] + b, fp16-split 3-pass, ldmatrix loads.
// Double-buffered A staging: ONE __syncthreads per k-tile.
// smem layout: [Ahi0 | Ahi1 | Alo0 | Alo1 | Bhi | Blo]
// ---------------------------------------------------------------------------
template <int BN>
__global__ void __launch_bounds__(256, 2)
gemm_ldm_kernel(const float* __restrict__ X, const __half* __restrict__ Whi,
                const __half* __restrict__ Wlo, const float* __restrict__ bias,
                float* __restrict__ Y, int N) {
    constexpr int K  = 128;
    constexpr int BM = 128;
    constexpr int BK = 16;
    constexpr int AP = 24;
    constexpr int KP = K + 8;
    constexpr int WN = BN / 2;
    constexpr int FRAG_M = 2;
    constexpr int FRAG_N = WN / 8;
    constexpr int ABUF = BM * AP;
    constexpr int NT = K / BK;

    extern __shared__ __half sm[];
    __half* Bhi = sm + 4 * ABUF;
    __half* Blo = Bhi + BN * KP;

    int tid  = threadIdx.x;
    int wid  = tid >> 5;
    int lane = tid & 31;
    int warp_m = wid & 3;
    int warp_n = wid >> 2;
    int row0 = blockIdx.x * BM;

    for (int idx = tid * 8; idx < BN * K; idx += 256 * 8) {
        int n = idx >> 7;
        int k = idx & 127;
        *(uint4*)&Bhi[n * KP + k] = *(const uint4*)&Whi[idx];
        *(uint4*)&Blo[n * KP + k] = *(const uint4*)&Wlo[idx];
    }

    float c[FRAG_M][FRAG_N][4];
    #pragma unroll
    for (int i = 0; i < FRAG_M; ++i)
        #pragma unroll
        for (int j = 0; j < FRAG_N; ++j)
            #pragma unroll
            for (int k = 0; k < 4; ++k) c[i][j][k] = 0.f;

    int xr  = tid >> 1;
    int xkb = (tid & 1) * 8;
    bool xvalid = (row0 + xr) < N;
    const float* xb = X + (size_t)(row0 + xr) * K + xkb;

    uint32_t a_hi_ad[2][FRAG_M], a_lo_ad[2][FRAG_M];
    #pragma unroll
    for (int b = 0; b < 2; ++b)
        #pragma unroll
        for (int fm = 0; fm < FRAG_M; ++fm) {
            int r = warp_m * 32 + fm * 16 + (lane & 15);
            int kofs = (lane >> 4) * 8;
            a_hi_ad[b][fm] = smaddr(&sm[b * ABUF + r * AP + kofs]);
            a_lo_ad[b][fm] = smaddr(&sm[2 * ABUF + b * ABUF + r * AP + kofs]);
        }
    int bn_row = warp_n * WN + (lane & 7);
    int bk_off = ((lane >> 3) & 1) * 8;

    float4 v0 = make_float4(0.f, 0.f, 0.f, 0.f), v1 = v0;
    if (xvalid) { v0 = *(const float4*)(xb); v1 = *(const float4*)(xb + 4); }
    {
        float va[8] = {v0.x, v0.y, v0.z, v0.w, v1.x, v1.y, v1.z, v1.w};
        uint4 uh, ul;
        split8(va, uh, ul);
        *(uint4*)&sm[0 * ABUF + xr * AP + xkb] = uh;
        *(uint4*)&sm[2 * ABUF + xr * AP + xkb] = ul;
    }
    if (xvalid) { v0 = *(const float4*)(xb + BK); v1 = *(const float4*)(xb + BK + 4); }
    __syncthreads();

    for (int t = 0; t < NT; ++t) {
        int kt = t * BK;
        int cur = t & 1;

        uint32_t ah[FRAG_M][4], al[FRAG_M][4];
        #pragma unroll
        for (int fm = 0; fm < FRAG_M; ++fm) {
            ldsm_x4(ah[fm], a_hi_ad[cur][fm]);
            ldsm_x4(al[fm], a_lo_ad[cur][fm]);
        }
        uint32_t bh[FRAG_N][2], bl[FRAG_N][2];
        #pragma unroll
        for (int fn = 0; fn < FRAG_N; ++fn) {
            int nr = (bn_row + fn * 8) * KP + kt + bk_off;
            ldsm_x2(bh[fn], smaddr(&Bhi[nr]));
            ldsm_x2(bl[fn], smaddr(&Blo[nr]));
        }

        if (t + 1 < NT) {
            int nxt = cur ^ 1;
            float va[8] = {v0.x, v0.y, v0.z, v0.w, v1.x, v1.y, v1.z, v1.w};
            uint4 uh, ul;
            split8(va, uh, ul);
            *(uint4*)&sm[nxt * ABUF + xr * AP + xkb] = uh;
            *(uint4*)&sm[2 * ABUF + nxt * ABUF + xr * AP + xkb] = ul;
            if (t + 2 < NT && xvalid) {
                v0 = *(const float4*)(xb + (t + 2) * BK);
                v1 = *(const float4*)(xb + (t + 2) * BK + 4);
            }
        }

        #pragma unroll
        for (int fm = 0; fm < FRAG_M; ++fm)
            #pragma unroll
            for (int fn = 0; fn < FRAG_N; ++fn) {
                mma_f16(c[fm][fn], ah[fm], bh[fn]);
                mma_f16(c[fm][fn], ah[fm], bl[fn]);
                mma_f16(c[fm][fn], al[fm], bh[fn]);
            }
        __syncthreads();
    }

    int er  = row0 + warp_m * 32 + (lane >> 2);
    int ec0 = warp_n * WN + (lane & 3) * 2;
    #pragma unroll
    for (int fn = 0; fn < FRAG_N; ++fn) {
        int col = ec0 + fn * 8;
        float b0 = bias[col], b1 = bias[col + 1];
        #pragma unroll
        for (int fm = 0; fm < FRAG_M; ++fm) {
            int r = er + fm * 16;
            if (r < N) {
                float2 o = make_float2(c[fm][fn][0] + b0, c[fm][fn][1] + b1);
                *(float2*)&Y[(size_t)r * BN + col] = o;
            }
            if (r + 8 < N) {
                float2 o = make_float2(c[fm][fn][2] + b0, c[fm][fn][3] + b1);
                *(float2*)&Y[(size_t)(r + 8) * BN + col] = o;
            }
        }
    }
}

// ---------------------------------------------------------------------------
// Fused dual-node-set attention logits: one launch covers papers AND authors.
// i < Np*4 -> paper table, else author table.  Same per-thread work as before.
// ---------------------------------------------------------------------------
template <int F>
__global__ void alpha2_dual_kernel(const float* __restrict__ Hp, const float* __restrict__ Ha,
                                   const float* __restrict__ avs_p, const float* __restrict__ avd_p,
                                   const float* __restrict__ avs_a, const float* __restrict__ avd_a,
                                   float* __restrict__ outs_p, float* __restrict__ outd_p,
                                   float* __restrict__ outs_a, float* __restrict__ outd_a,
                                   int Np, int Na) {
    int i = blockIdx.x * blockDim.x + threadIdx.x;
    int totp = Np * H4;
    const float* Hf; const float* avs; const float* avd; float* outs; float* outd;
    int idx;
    if (i < totp) {
        Hf = Hp; avs = avs_p; avd = avd_p; outs = outs_p; outd = outd_p; idx = i;
    } else {
        idx = i - totp;
        if (idx >= Na * H4) return;
        Hf = Ha; avs = avs_a; avd = avd_a; outs = outs_a; outd = outd_a;
    }
    int n = idx >> 2, h = idx & 3;
    constexpr int D = F / 4;
    const float4* row = (const float4*)(Hf + (size_t)n * F + h * D);
    const float4* as = (const float4*)(avs + h * D);
    const float4* ad = (const float4*)(avd + h * D);
    float ss = 0.f, sd = 0.f;
    #pragma unroll
    for (int d = 0; d < D / 4; ++d) {
        float4 hv = row[d], a = as[d], b = ad[d];
        ss += hv.x * a.x + hv.y * a.y + hv.z * a.z + hv.w * a.w;
        sd += hv.x * b.x + hv.y * b.y + hv.z * b.z + hv.w * b.w;
    }
    outs[idx] = ss;
    outd[idx] = sd;
}

// ---------------------------------------------------------------------------
// Edge-softmax aggregation, warp per dst node, BATCH-2 online softmax
// (measured best: R14).  Two edges per iteration, joint running max.
// ---------------------------------------------------------------------------
template <int F>
__global__ void __launch_bounds__(256)
aggregate_kernel(const float* __restrict__ Hsrc, const float* __restrict__ asrc,
                 const float* __restrict__ adst, const int* __restrict__ offs,
                 const int* __restrict__ srcs, float* __restrict__ Out, int Ndst) {
    constexpr int VEC = F / 32;
    int wid = (blockIdx.x * blockDim.x + threadIdx.x) >> 5;
    int lane = threadIdx.x & 31;
    if (wid >= Ndst) return;
    int beg = offs[wid], end = offs[wid + 1];
    int head = lane >> 3;
    float ad = __ldg(&adst[wid * H4 + head]);
    float m = -3.4e38f, l = 0.f;
    float acc[VEC];
    #pragma unroll
    for (int v = 0; v < VEC; ++v) acc[v] = 0.f;

    int j = beg;
    for (; j + 2 <= end; j += 2) {
        int s0 = __ldg(&srcs[j]);
        int s1 = __ldg(&srcs[j + 1]);
        float a0 = __ldg(&asrc[s0 * H4 + head]) + ad;
        float a1 = __ldg(&asrc[s1 * H4 + head]) + ad;
        a0 = (a0 >= 0.f) ? a0 : 0.2f * a0;
        a1 = (a1 >= 0.f) ? a1 : 0.2f * a1;
        float mn = fmaxf(m, fmaxf(a0, a1));
        float sc = __expf(m - mn);
        float e0 = __expf(a0 - mn);
        float e1 = __expf(a1 - mn);
        l = l * sc + e0 + e1;
        const float* p0 = Hsrc + (size_t)s0 * F + lane * VEC;
        const float* p1 = Hsrc + (size_t)s1 * F + lane * VEC;
        if (VEC == 4) {
            float4 h0 = __ldg((const float4*)p0);
            float4 h1 = __ldg((const float4*)p1);
            acc[0] = acc[0] * sc + e0 * h0.x + e1 * h1.x;
            acc[1] = acc[1] * sc + e0 * h0.y + e1 * h1.y;
            acc[2] = acc[2] * sc + e0 * h0.z + e1 * h1.z;
            acc[3] = acc[3] * sc + e0 * h0.w + e1 * h1.w;
        } else {
            float2 h0 = __ldg((const float2*)p0);
            float2 h1 = __ldg((const float2*)p1);
            acc[0] = acc[0] * sc + e0 * h0.x + e1 * h1.x;
            acc[1] = acc[1] * sc + e0 * h0.y + e1 * h1.y;
        }
        m = mn;
    }
    if (j < end) {
        int s = __ldg(&srcs[j]);
        float a = __ldg(&asrc[s * H4 + head]) + ad;
        a = (a >= 0.f) ? a : 0.2f * a;
        float mn = fmaxf(m, a);
        float sc = __expf(m - mn);
        float e  = __expf(a - mn);
        l = l * sc + e;
        const float* hp = Hsrc + (size_t)s * F + lane * VEC;
        if (VEC == 4) {
            float4 hv = __ldg((const float4*)hp);
            acc[0] = acc[0] * sc + e * hv.x;
            acc[1] = acc[1] * sc + e * hv.y;
            acc[2] = acc[2] * sc + e * hv.z;
            acc[3] = acc[3] * sc + e * hv.w;
        } else {
            float2 hv = __ldg((const float2*)hp);
            acc[0] = acc[0] * sc + e * hv.x;
            acc[1] = acc[1] * sc + e * hv.y;
        }
        m = mn;
    }
    float inv = 1.f / (l + 1e-16f);
    float* op = Out + (size_t)wid * F + lane * VEC;
    #pragma unroll
    for (int v = 0; v < VEC; ++v) op[v] = fmaxf(acc[v] * inv, 0.f);
}

// ---------------------------------------------------------------------------
// Final link prediction: 8 lanes per edge, 2 float4 loads each (4 loads in
// flight per lane pair), 3-stage shfl reduction.
// ---------------------------------------------------------------------------
__global__ void edge_dot_kernel(const float* __restrict__ zp, const float* __restrict__ za,
                                const int* __restrict__ eli, float* __restrict__ out, int L) {
    int t = blockIdx.x * blockDim.x + threadIdx.x;
    int edge = t >> 3;
    int sub = t & 7;
    if (edge >= L) return;
    int p = __ldg(&eli[edge]);
    int a = __ldg(&eli[L + edge]);
    const float* pp = zp + (size_t)p * 64 + sub * 8;
    const float* pa = za + (size_t)a * 64 + sub * 8;
    float4 u0 = __ldg((const float4*)pp);
    float4 u1 = __ldg((const float4*)(pp + 4));
    float4 v0 = __ldg((const float4*)pa);
    float4 v1 = __ldg((const float4*)(pa + 4));
    float s = u0.x * v0.x + u0.y * v0.y + u0.z * v0.z + u0.w * v0.w
            + u1.x * v1.x + u1.y * v1.y + u1.z * v1.z + u1.w * v1.w;
    s += __shfl_xor_sync(0xffffffffu, s, 4);
    s += __shfl_xor_sync(0xffffffffu, s, 2);
    s += __shfl_xor_sync(0xffffffffu, s, 1);
    if (sub == 0) out[edge] = s;
}

// ---------------------------------------------------------------------------
// Host orchestration  (R13/R14 schedule, measured best)
// ---------------------------------------------------------------------------
extern "C" void kernel_launch(void* const* d_in, const int* in_sizes, int n_in,
                              void* d_out, int out_size) {
    const float* x_paper  = (const float*)d_in[0];
    const float* x_author = (const float*)d_in[1];
    const int*   ei_pa    = (const int*)d_in[2];
    const int*   ei_ap    = (const int*)d_in[3];
    const int*   eli      = (const int*)d_in[4];
    const float* p1W = (const float*)d_in[5];
    const float* p1b = (const float*)d_in[6];
    const float* a1W = (const float*)d_in[7];
    const float* a1b = (const float*)d_in[8];
    const float* s1pa = (const float*)d_in[9];
    const float* d1pa = (const float*)d_in[10];
    const float* s1ap = (const float*)d_in[11];
    const float* d1ap = (const float*)d_in[12];
    // d_in[13..15]: k1W,k1b,q1 dead (_group over one metapath == identity)
    const float* p2W = (const float*)d_in[16];
    const float* p2b = (const float*)d_in[17];
    const float* a2W = (const float*)d_in[18];
    const float* a2b = (const float*)d_in[19];
    const float* s2pa = (const float*)d_in[20];
    const float* d2pa = (const float*)d_in[21];
    const float* s2ap = (const float*)d_in[22];
    const float* d2ap = (const float*)d_in[23];
    // d_in[24..26]: k2W,k2b,q2 dead

    int NP = in_sizes[0] / 128;
    int NA = in_sizes[1] / 128;
    int E  = in_sizes[2] / 2;
    int L  = in_sizes[4] / 2;

    float *hp, *ha, *ha2, *zp, *za, *asrc_pa, *adst_pa, *asrc_ap, *adst_ap;
    int *offs_pa, *offs_ap, *srcs_pa, *srcs_ap, *cnt, *cnt2, *partials, *partials2;
    __half *wh, *wl;
    cudaGetSymbolAddress((void**)&hp, g_hp);
    cudaGetSymbolAddress((void**)&ha, g_ha);
    cudaGetSymbolAddress((void**)&ha2, g_ha2);
    cudaGetSymbolAddress((void**)&zp, g_zp);
    cudaGetSymbolAddress((void**)&za, g_za);
    cudaGetSymbolAddress((void**)&asrc_pa, g_asrc_pa);
    cudaGetSymbolAddress((void**)&adst_pa, g_adst_pa);
    cudaGetSymbolAddress((void**)&asrc_ap, g_asrc_ap);
    cudaGetSymbolAddress((void**)&adst_ap, g_adst_ap);
    cudaGetSymbolAddress((void**)&offs_pa, g_offs_pa);
    cudaGetSymbolAddress((void**)&offs_ap, g_offs_ap);
    cudaGetSymbolAddress((void**)&srcs_pa, g_srcs_pa);
    cudaGetSymbolAddress((void**)&srcs_ap, g_srcs_ap);
    cudaGetSymbolAddress((void**)&cnt, g_cnt);
    cudaGetSymbolAddress((void**)&cnt2, g_cnt2);
    cudaGetSymbolAddress((void**)&partials, g_partials);
    cudaGetSymbolAddress((void**)&partials2, g_partials2);
    cudaGetSymbolAddress((void**)&wh, g_wh);
    cudaGetSymbolAddress((void**)&wl, g_wl);
    __half* wh1p = wh;               __half* wl1p = wl;
    __half* wh1a = wh + 16384;       __half* wl1a = wl + 16384;
    __half* wh2p = wh + 2 * 16384;   __half* wl2p = wl + 2 * 16384;
    __half* wh2a = wh + 3 * 16384;   __half* wl2a = wl + 3 * 16384;

    // smem: 4 A buffers (double-buffered hi/lo) + B hi/lo
    constexpr int SM128 = (4 * 128 * 24 + 2 * 128 * 136) * 2;   // 94208
    constexpr int SM64  = (4 * 128 * 24 + 2 * 64 * 136) * 2;    // 59392
    cudaFuncSetAttribute(gemm_ldm_kernel<128>, cudaFuncAttributeMaxDynamicSharedMemorySize, SM128);
    cudaFuncSetAttribute(gemm_ldm_kernel<64>,  cudaFuncAttributeMaxDynamicSharedMemorySize, SM64);

    static cudaStream_t s1 = nullptr;
    static cudaEvent_t evA = nullptr, evB = nullptr, evC = nullptr, evD = nullptr;
    if (!s1) {
        cudaStreamCreateWithFlags(&s1, cudaStreamNonBlocking);
        cudaEventCreateWithFlags(&evA, cudaEventDisableTiming);
        cudaEventCreateWithFlags(&evB, cudaEventDisableTiming);
        cudaEventCreateWithFlags(&evC, cudaEventDisableTiming);
        cudaEventCreateWithFlags(&evD, cudaEventDisableTiming);
    }

    int gb_p = (NP + 127) / 128;
    int gb_a = (NA + 127) / 128;
    int at_2 = ((NP + NA) * H4 + 255) / 256;
    int ag_a = (NA * 32 + 255) / 256;
    int ag_p = (NP * 32 + 255) / 256;
    int nb   = (NMAX + 1023) / 1024;
    int ws128 = (128 * 16 + 255) / 256;
    int ws64  = (64 * 16 + 255) / 256;
    int eg   = (E + 255) / 256;

    // ---- main stream: kernels 1-3, then the captured GEMM (#4) ----
    wsplit_kernel<<<ws128, 256>>>(p1W, wh1p, wl1p, 128, 128);                 // k1
    hist_kernel<<<eg, 256>>>(ei_pa + E, E, cnt);                              // k2 (cnt zero on entry)
    scan_phase1<<<nb, 1024>>>(cnt, NA, offs_pa, partials);                    // k3
    gemm_ldm_kernel<128><<<gb_p, 256, SM128>>>(x_paper, wh1p, wl1p, p1b, hp, NP);  // k4 <- ncu
    cudaEventRecord(evA, 0);

    // ---- side stream: CSR-ap + layer-2 weight splits (hidden by gemms) ----
    cudaStreamWaitEvent(s1, evA, 0);
    cudaMemsetAsync(cnt2, 0, (size_t)NP * sizeof(int), s1);
    hist_kernel<<<eg, 256, 0, s1>>>(ei_ap + E, E, cnt2);
    scan_phase1<<<nb, 1024, 0, s1>>>(cnt2, NP, offs_ap, partials2);
    scan_phase2<<<1, 256, 0, s1>>>(partials2, nb);
    scan_phase3<<<nb, 1024, 0, s1>>>(offs_ap, partials2, NP);
    cudaMemcpyAsync(cnt2, offs_ap, (size_t)NP * sizeof(int), cudaMemcpyDeviceToDevice, s1);
    scatter_kernel<<<eg, 256, 0, s1>>>(ei_ap, ei_ap + E, E, cnt2, srcs_ap);
    wsplit_kernel<<<ws64, 256, 0, s1>>>(p2W, wh2p, wl2p, 128, 64);
    wsplit_kernel<<<ws64, 256, 0, s1>>>(a2W, wh2a, wl2a, 128, 64);
    cudaEventRecord(evB, s1);

    // ---- main: finish CSR-pa, 2nd gemm, attention ----
    scan_phase2<<<1, 256>>>(partials, nb);
    scan_phase3<<<nb, 1024>>>(offs_pa, partials, NA);
    cudaMemcpyAsync(cnt, offs_pa, (size_t)NA * sizeof(int), cudaMemcpyDeviceToDevice);
    scatter_kernel<<<eg, 256>>>(ei_pa, ei_pa + E, E, cnt, srcs_pa);
    cudaMemsetAsync(cnt, 0, (size_t)NA * sizeof(int));   // re-zero for next call
    wsplit_kernel<<<ws128, 256>>>(a1W, wh1a, wl1a, 128, 128);
    gemm_ldm_kernel<128><<<gb_a, 256, SM128>>>(x_author, wh1a, wl1a, a1b, ha, NA);

    // fused alpha for both node sets (one launch)
    alpha2_dual_kernel<128><<<at_2, 256>>>(hp, ha, s1pa, d1ap, s1ap, d1pa,
                                           asrc_pa, adst_ap, asrc_ap, adst_pa, NP, NA);
    aggregate_kernel<128><<<ag_a, 256>>>(hp, asrc_pa, adst_pa, offs_pa, srcs_pa, za, NA);
    cudaEventRecord(evC, 0);          // za ready

    // side: gemm2a (za -> ha2, dedicated buffer) overlaps agg_ap + gemm2p
    cudaStreamWaitEvent(s1, evC, 0);
    gemm_ldm_kernel<64><<<gb_a, 256, SM64, s1>>>(za, wh2a, wl2a, a2b, ha2, NA);
    cudaEventRecord(evD, s1);

    cudaStreamWaitEvent(0, evB, 0);   // CSR-ap ready
    aggregate_kernel<128><<<ag_p, 256>>>(ha, asrc_ap, adst_ap, offs_ap, srcs_ap, zp, NP);

    // ---- Layer 2 (K=128 -> F=64) ----
    gemm_ldm_kernel<64><<<gb_p, 256, SM64>>>(zp, wh2p, wl2p, p2b, hp, NP);
    cudaStreamWaitEvent(0, evD, 0);   // ha2 ready (also guards za overwrite below)
    alpha2_dual_kernel<64><<<at_2, 256>>>(hp, ha2, s2pa, d2ap, s2ap, d2pa,
                                          asrc_pa, adst_ap, asrc_ap, adst_pa, NP, NA);
    aggregate_kernel<64><<<ag_a, 256>>>(hp, asrc_pa, adst_pa, offs_pa, srcs_pa, za, NA);
    aggregate_kernel<64><<<ag_p, 256>>>(ha2, asrc_ap, adst_ap, offs_ap, srcs_ap, zp, NP);

    // ---- Link prediction ----
    edge_dot_kernel<<<(L * 8 + 255) / 256, 256>>>(zp, za, eli, (float*)d_out, L);
}